// round 12
// baseline (speedup 1.0000x reference)
#include <cuda_runtime.h>
#include <cuda_bf16.h>
#include <math.h>
#include <stdint.h>

#define NUM_USER 200000
#define NUM_ITEM 200000
#define DIM_E    64
#define DIM_F    128
#define HID      256
#define BATCH    16384
#define GRP      17
#define NTOT     (BATCH * GRP)   // 278528

#define MTILE    128
#define THREADS  512
#define AS_LDW   68    // As pitch in 32-bit words (64 data + 4 pad), 68%32==4
#define HS_LDW   132   // Hs pitch (128 data + 4 pad), 132%32==4
#define W1_LDW   68    // packed W1 pitch per col (64 data + 4 pad)
#define W2_LDW   132   // packed W2 pitch per col (128 data + 4 pad)

#define WP1_WORDS (HID * W1_LDW)      // 17408
#define WP2_WORDS (DIM_E * W2_LDW)    //  8448
#define AS_WORDS  (MTILE * AS_LDW)    //  8704
#define HS_WORDS  (MTILE * HS_LDW)    // 16896
#define SMEM_WORDS (WP1_WORDS + WP2_WORDS + AS_WORDS + HS_WORDS + HID + DIM_E)

// Scratch (static device globals: allocation-free per harness rules)
__device__ float         g_feature[(size_t)NUM_ITEM * DIM_E];  // 51.2 MB
__device__ unsigned int  g_wp1[WP1_WORDS];
__device__ unsigned int  g_wp2[WP2_WORDS];
__device__ unsigned char g_mask[NTOT];
__device__ float         g_accum[2];

// ---------------------------------------------------------------------------
__device__ __forceinline__ uint32_t pk_bf16x2(float lo, float hi) {
    __nv_bfloat162 h = __floats2bfloat162_rn(lo, hi);   // .x = lo (low half)
    return *reinterpret_cast<uint32_t*>(&h);
}

__device__ __forceinline__ void mma_bf16(float* c, const uint32_t* a,
                                         uint32_t b0, uint32_t b1) {
    asm volatile(
        "mma.sync.aligned.m16n8k16.row.col.f32.bf16.bf16.f32 "
        "{%0,%1,%2,%3},{%4,%5,%6,%7},{%8,%9},{%0,%1,%2,%3};"
        : "+f"(c[0]), "+f"(c[1]), "+f"(c[2]), "+f"(c[3])
        : "r"(a[0]), "r"(a[1]), "r"(a[2]), "r"(a[3]), "r"(b0), "r"(b1));
}

__device__ __forceinline__ void ldsm_x4(uint32_t* a, const uint32_t* p) {
    uint32_t s = (uint32_t)__cvta_generic_to_shared(p);
    asm volatile("ldmatrix.sync.aligned.m8n8.x4.shared.b16 {%0,%1,%2,%3},[%4];"
                 : "=r"(a[0]), "=r"(a[1]), "=r"(a[2]), "=r"(a[3]) : "r"(s));
}

__device__ __forceinline__ void cp_async16(void* dst, const void* src) {
    uint32_t s = (uint32_t)__cvta_generic_to_shared(dst);
    asm volatile("cp.async.ca.shared.global [%0], [%1], 16;" :: "r"(s), "l"(src));
}
__device__ __forceinline__ void cp_commit() { asm volatile("cp.async.commit_group;"); }
__device__ __forceinline__ void cp_wait0()  { asm volatile("cp.async.wait_group 0;"); }

// ---------------------------------------------------------------------------
__global__ void zero_kernel() {
    int i = blockIdx.x * blockDim.x + threadIdx.x;
    if (i < NTOT / 4) ((unsigned int*)g_mask)[i] = 0u;
    if (i < 2) g_accum[i] = 0.0f;
}

__global__ void scatter_kernel(const int* __restrict__ rand_index, int n) {
    int i = blockIdx.x * blockDim.x + threadIdx.x;
    if (i < n) g_mask[rand_index[i]] = 1;
}

// Pack weights into bf16x2 B-fragment layout (col-major, padded pitch).
__global__ void pack_kernel(const float* __restrict__ W1,
                            const float* __restrict__ W2) {
    int i = blockIdx.x * blockDim.x + threadIdx.x;
    if (i < WP1_WORDS) {
        int col = i / W1_LDW, w = i % W1_LDW;
        unsigned int v = 0u;
        if (w < DIM_F / 2)
            v = pk_bf16x2(W1[(size_t)(2 * w) * HID + col],
                          W1[(size_t)(2 * w + 1) * HID + col]);
        g_wp1[i] = v;
    }
    int j = i - WP1_WORDS;
    if (j >= 0 && j < WP2_WORDS) {
        int col = j / W2_LDW, w = j % W2_LDW;
        unsigned int v = 0u;
        if (w < HID / 2)
            v = pk_bf16x2(W2[(size_t)(2 * w) * DIM_E + col],
                          W2[(size_t)(2 * w + 1) * DIM_E + col]);
        g_wp2[j] = v;
    }
}

// ---------------------------------------------------------------------------
// BF16 tensor-core encoder. CTA = 128 rows, 16 warps. All frags via ldmatrix.
// Layer1 (128x256x128): warps 2m x 8n, warp tile 64x32 (mt=4, nt=4).
// Layer2 (128x 64x256): warps 4m x 4n, warp tile 32x16 (mt=2, nt=2).
// ---------------------------------------------------------------------------
__global__ void __launch_bounds__(THREADS, 1) encoder_kernel(
    const float* __restrict__ v_feat,
    const float* __restrict__ b1, const float* __restrict__ b2)
{
    extern __shared__ uint32_t smu[];
    uint32_t* Wp1s = smu;                       // [256][W1_LDW]
    uint32_t* Wp2s = Wp1s + WP1_WORDS;          // [ 64][W2_LDW]
    uint32_t* As   = Wp2s + WP2_WORDS;          // [128][AS_LDW]
    uint32_t* Hs   = As + AS_WORDS;             // [128][HS_LDW]
    float*    b1s  = (float*)(Hs + HS_WORDS);   // [256]
    float*    b2s  = b1s + HID;                 // [64]

    const int tid  = threadIdx.x;
    const int lane = tid & 31;
    const int warp = tid >> 5;
    const int g    = lane >> 2;       // 0..7
    const int t    = lane & 3;        // 0..3
    const int lrow = lane & 7;        // ldmatrix row-in-tile
    const int lsel = lane >> 3;       // ldmatrix matrix select 0..3
    const int row0 = blockIdx.x * MTILE;

    // ---- stream all packed weights into SMEM (linear cp.async) ----
    for (int i = tid; i < WP1_WORDS / 4; i += THREADS)
        cp_async16(Wp1s + i * 4, g_wp1 + i * 4);
    for (int i = tid; i < WP2_WORDS / 4; i += THREADS)
        cp_async16(Wp2s + i * 4, g_wp2 + i * 4);
    cp_commit();

    if (tid < HID)   b1s[tid] = b1[tid];
    if (tid < DIM_E) b2s[tid] = b2[tid];

    // ---- stage + l2-normalize 128 rows into As as bf16x2 ----
    #pragma unroll
    for (int i = 0; i < 8; i++) {
        int r = warp * 8 + i;
        int grow = row0 + r;
        int gc = min(grow, NUM_ITEM - 1);
        float4 v = ((const float4*)(v_feat + (size_t)gc * DIM_F))[lane];
        float ss = v.x * v.x + v.y * v.y + v.z * v.z + v.w * v.w;
        #pragma unroll
        for (int o = 16; o; o >>= 1) ss += __shfl_xor_sync(0xffffffffu, ss, o);
        float inv = 1.0f / fmaxf(sqrtf(ss), 1e-12f);
        uint2 w2;
        w2.x = pk_bf16x2(v.x * inv, v.y * inv);
        w2.y = pk_bf16x2(v.z * inv, v.w * inv);
        *(uint2*)(As + r * AS_LDW + lane * 2) = w2;
    }

    cp_wait0();
    __syncthreads();

    // ================= layer 1: warps 2m x 8n, tile 64x32 =================
    const int mrow  = (warp >> 3) * 64;    // 0 or 64
    const int nbase = (warp & 7) * 32;     // 0..224
    float acc1[4][4][4];
    #pragma unroll
    for (int mt = 0; mt < 4; mt++)
        #pragma unroll
        for (int nt = 0; nt < 4; nt++)
            #pragma unroll
            for (int q = 0; q < 4; q++) acc1[mt][nt][q] = 0.0f;

    // B ldmatrix lane mapping: sub = lsel (0..3): tile = 2*bm + (sub>>1), khalf = sub&1
    const int bcol1 = (lsel >> 1) * 8 + lrow;   // col offset within 16-col group
    const int bkh   = (lsel & 1) * 4;           // khalf word offset

    #pragma unroll
    for (int ks = 0; ks < DIM_F / 16; ks++) {        // 8 k-steps of 16
        uint32_t a[4][4];
        #pragma unroll
        for (int mt = 0; mt < 4; mt++)
            ldsm_x4(a[mt], As + (mrow + mt * 16 + lrow + (lsel & 1) * 8) * AS_LDW
                              + ks * 8 + (lsel >> 1) * 4);
        #pragma unroll
        for (int bm = 0; bm < 2; bm++) {             // each covers 2 n-tiles
            uint32_t bb[4];
            ldsm_x4(bb, Wp1s + (nbase + bm * 16 + bcol1) * W1_LDW + ks * 8 + bkh);
            #pragma unroll
            for (int n2 = 0; n2 < 2; n2++) {
                int nt = bm * 2 + n2;
                #pragma unroll
                for (int mt = 0; mt < 4; mt++)
                    mma_bf16(acc1[mt][nt], a[mt], bb[n2 * 2], bb[n2 * 2 + 1]);
            }
        }
    }

    // epilogue 1: bias + leaky_relu -> Hs (bf16x2, word w = hidden cols 2w,2w+1)
    #pragma unroll
    for (int mt = 0; mt < 4; mt++) {
        #pragma unroll
        for (int nt = 0; nt < 4; nt++) {
            int r   = mrow + mt * 16 + g;
            int col = nbase + nt * 8 + 2 * t;
            float x0 = acc1[mt][nt][0] + b1s[col];
            float x1 = acc1[mt][nt][1] + b1s[col + 1];
            float x2 = acc1[mt][nt][2] + b1s[col];
            float x3 = acc1[mt][nt][3] + b1s[col + 1];
            x0 = (x0 > 0.0f) ? x0 : 0.01f * x0;
            x1 = (x1 > 0.0f) ? x1 : 0.01f * x1;
            x2 = (x2 > 0.0f) ? x2 : 0.01f * x2;
            x3 = (x3 > 0.0f) ? x3 : 0.01f * x3;
            int wofs = (nbase >> 1) + nt * 4 + t;
            Hs[r * HS_LDW + wofs]       = pk_bf16x2(x0, x1);
            Hs[(r + 8) * HS_LDW + wofs] = pk_bf16x2(x2, x3);
        }
    }
    __syncthreads();

    // ================= layer 2: warps 4m x 4n, tile 32x16 =================
    const int mrow2 = (warp >> 2) * 32;    // 0..96
    const int nb2   = (warp & 3) * 16;     // 0..48
    float acc2[2][2][4];
    #pragma unroll
    for (int mt = 0; mt < 2; mt++)
        #pragma unroll
        for (int nt = 0; nt < 2; nt++)
            #pragma unroll
            for (int q = 0; q < 4; q++) acc2[mt][nt][q] = 0.0f;

    #pragma unroll
    for (int ks = 0; ks < HID / 16; ks++) {          // 16 k-steps
        uint32_t h[2][4];
        #pragma unroll
        for (int mt = 0; mt < 2; mt++)
            ldsm_x4(h[mt], Hs + (mrow2 + mt * 16 + lrow + (lsel & 1) * 8) * HS_LDW
                              + ks * 8 + (lsel >> 1) * 4);
        uint32_t bb[4];   // 2 n-tiles x {b0,b1}
        ldsm_x4(bb, Wp2s + (nb2 + bcol1) * W2_LDW + ks * 8 + bkh);
        #pragma unroll
        for (int nt = 0; nt < 2; nt++) {
            #pragma unroll
            for (int mt = 0; mt < 2; mt++)
                mma_bf16(acc2[mt][nt], h[mt], bb[nt * 2], bb[nt * 2 + 1]);
        }
    }

    // epilogue 2: + b2 -> g_feature (guard tail rows)
    #pragma unroll
    for (int mt = 0; mt < 2; mt++) {
        #pragma unroll
        for (int nt = 0; nt < 2; nt++) {
            int r   = row0 + mrow2 + mt * 16 + g;
            int col = nb2 + nt * 8 + 2 * t;
            float2 lo = make_float2(acc2[mt][nt][0] + b2s[col],
                                    acc2[mt][nt][1] + b2s[col + 1]);
            float2 hi = make_float2(acc2[mt][nt][2] + b2s[col],
                                    acc2[mt][nt][3] + b2s[col + 1]);
            if (r < NUM_ITEM)
                *(float2*)(g_feature + (size_t)r * DIM_E + col) = lo;
            if (r + 8 < NUM_ITEM)
                *(float2*)(g_feature + (size_t)(r + 8) * DIM_E + col) = hi;
        }
    }
}

// ---------------------------------------------------------------------------
// Loss: one warp per batch row (17 pairs). Lanes cover 64 dims as float2.
// ---------------------------------------------------------------------------
__global__ void __launch_bounds__(256) loss_kernel(
    const float* __restrict__ id_emb,
    const int*   __restrict__ user_t,
    const int*   __restrict__ item_t)
{
    __shared__ float bs[2];
    if (threadIdx.x == 0) { bs[0] = 0.0f; bs[1] = 0.0f; }
    __syncthreads();

    int warp = (blockIdx.x * blockDim.x + threadIdx.x) >> 5;
    int lane = threadIdx.x & 31;

    if (warp < BATCH) {
        int base = warp * GRP;
        int pit  = item_t[base];
        float2 pe = ((const float2*)(id_emb + (size_t)pit * DIM_E))[lane];
        float ps = fmaf(pe.x, pe.x, pe.y * pe.y);
        #pragma unroll
        for (int o = 16; o; o >>= 1) ps += __shfl_xor_sync(0xffffffffu, ps, o);
        float inv_p = 1.0f / fmaxf(sqrtf(ps), 1e-12f);

        float tot1 = 0.0f, tot2 = 0.0f, pos1 = 0.0f, pos2 = 0.0f;
        #pragma unroll 4
        for (int gi = 0; gi < GRP; ++gi) {
            int it = item_t[base + gi];
            int u  = user_t[base + gi];
            int item = it - NUM_USER;
            item = min(max(item, 0), NUM_ITEM - 1);

            float2 f  = ((const float2*)(g_feature + (size_t)item * DIM_E))[lane];
            float2 ue = ((const float2*)(id_emb + (size_t)u * DIM_E))[lane];
            float2 av;
            if (g_mask[base + gi]) av = f;
            else av = ((const float2*)(id_emb + (size_t)it * DIM_E))[lane];

            float fn = fmaf(f.x, f.x, f.y * f.y);
            float d1 = fmaf(pe.x, f.x, pe.y * f.y);
            float d2 = fmaf(ue.x, av.x, ue.y * av.y);
            #pragma unroll
            for (int o = 16; o; o >>= 1) {
                fn += __shfl_xor_sync(0xffffffffu, fn, o);
                d1 += __shfl_xor_sync(0xffffffffu, d1, o);
                d2 += __shfl_xor_sync(0xffffffffu, d2, o);
            }
            float inv_f = 1.0f / fmaxf(sqrtf(fn), 1e-12f);
            float s1 = expf(d1 * inv_p * inv_f * 5.0f);
            float s2 = expf(d2 * 5.0f);
            tot1 += s1; tot2 += s2;
            if (gi == 0) { pos1 = s1; pos2 = s2; }
        }
        if (lane == 0) {
            atomicAdd(&bs[0], -logf(pos1 / (tot1 + 1e-8f) + 1e-8f));
            atomicAdd(&bs[1], -logf(pos2 / (tot2 + 1e-8f) + 1e-8f));
        }
    }
    __syncthreads();
    if (threadIdx.x == 0) {
        atomicAdd(&g_accum[0], bs[0]);
        atomicAdd(&g_accum[1], bs[1]);
    }
}

// ---------------------------------------------------------------------------
__global__ void finalize_kernel(float* __restrict__ out, int n) {
    float v = (g_accum[0] + g_accum[1]) * (0.5f / (float)BATCH);
    for (int i = threadIdx.x; i < n; i += blockDim.x) out[i] = v;
}

// ---------------------------------------------------------------------------
extern "C" void kernel_launch(void* const* d_in, const int* in_sizes, int n_in,
                              void* d_out, int out_size)
{
    const float* v_feat = (const float*)d_in[0];
    const float* id_emb = (const float*)d_in[1];
    const float* W1     = (const float*)d_in[2];
    const float* b1     = (const float*)d_in[3];
    const float* W2     = (const float*)d_in[4];
    const float* b2     = (const float*)d_in[5];
    const int*   user_t = (const int*)d_in[6];
    const int*   item_t = (const int*)d_in[7];
    const int*   rand_i = (const int*)d_in[8];
    const int    n_rand = in_sizes[8];
    float*       out    = (float*)d_out;

    const size_t smem = (size_t)SMEM_WORDS * 4;   // ~207 KB
    cudaFuncSetAttribute(encoder_kernel,
                         cudaFuncAttributeMaxDynamicSharedMemorySize, (int)smem);

    zero_kernel<<<(NTOT / 4 + 255) / 256, 256>>>();
    scatter_kernel<<<(n_rand + 255) / 256, 256>>>(rand_i, n_rand);
    pack_kernel<<<(WP1_WORDS + WP2_WORDS + 255) / 256, 256>>>(W1, W2);
    encoder_kernel<<<(NUM_ITEM + MTILE - 1) / MTILE, THREADS, smem>>>(v_feat, b1, b2);
    loss_kernel<<<BATCH / 8, 256>>>(id_emb, user_t, item_t);
    finalize_kernel<<<1, 32>>>(out, out_size > 0 ? out_size : 1);
}

// round 15
// speedup vs baseline: 1.2969x; 1.2969x over previous
#include <cuda_runtime.h>
#include <cuda_bf16.h>
#include <math.h>
#include <stdint.h>

#define NUM_USER 200000
#define NUM_ITEM 200000
#define DIM_E    64
#define DIM_F    128
#define HID      256
#define BATCH    16384
#define GRP      17
#define NTOT     (BATCH * GRP)   // 278528

#define MTILE    128
#define THREADS  512
#define ENC_GRID 148
#define NTILES   ((NUM_ITEM + MTILE - 1) / MTILE)   // 1563

#define AS_LDW   68    // As pitch in 32-bit words (64 data + 4 pad), 68%32==4
#define HS_LDW   132   // Hs pitch (128 data + 4 pad), 132%32==4
#define W1_LDW   68    // packed W1 pitch per col (64 data + 4 pad)
#define W2_LDW   132   // packed W2 pitch per col (128 data + 4 pad)

#define WP1_WORDS (HID * W1_LDW)      // 17408
#define WP2_WORDS (DIM_E * W2_LDW)    //  8448
#define AS_WORDS  (MTILE * AS_LDW)    //  8704
#define HS_WORDS  (MTILE * HS_LDW)    // 16896
#define SMEM_WORDS (WP1_WORDS + WP2_WORDS + AS_WORDS + HS_WORDS + HID + DIM_E)

// Scratch (static device globals: allocation-free per harness rules)
__device__ float         g_feature[(size_t)NUM_ITEM * DIM_E];  // 51.2 MB
__device__ unsigned int  g_wp1[WP1_WORDS];
__device__ unsigned int  g_wp2[WP2_WORDS];
__device__ unsigned char g_mask[NTOT];
__device__ float         g_accum[2];

// ---------------------------------------------------------------------------
__device__ __forceinline__ uint32_t pk_bf16x2(float lo, float hi) {
    __nv_bfloat162 h = __floats2bfloat162_rn(lo, hi);   // .x = lo (low half)
    return *reinterpret_cast<uint32_t*>(&h);
}

__device__ __forceinline__ void mma_bf16(float* c, const uint32_t* a,
                                         uint32_t b0, uint32_t b1) {
    asm volatile(
        "mma.sync.aligned.m16n8k16.row.col.f32.bf16.bf16.f32 "
        "{%0,%1,%2,%3},{%4,%5,%6,%7},{%8,%9},{%0,%1,%2,%3};"
        : "+f"(c[0]), "+f"(c[1]), "+f"(c[2]), "+f"(c[3])
        : "r"(a[0]), "r"(a[1]), "r"(a[2]), "r"(a[3]), "r"(b0), "r"(b1));
}

__device__ __forceinline__ void ldsm_x4(uint32_t* a, const uint32_t* p) {
    uint32_t s = (uint32_t)__cvta_generic_to_shared(p);
    asm volatile("ldmatrix.sync.aligned.m8n8.x4.shared.b16 {%0,%1,%2,%3},[%4];"
                 : "=r"(a[0]), "=r"(a[1]), "=r"(a[2]), "=r"(a[3]) : "r"(s));
}

__device__ __forceinline__ void cp_async16(void* dst, const void* src) {
    uint32_t s = (uint32_t)__cvta_generic_to_shared(dst);
    asm volatile("cp.async.ca.shared.global [%0], [%1], 16;" :: "r"(s), "l"(src));
}
__device__ __forceinline__ void cp_commit() { asm volatile("cp.async.commit_group;"); }
__device__ __forceinline__ void cp_wait0()  { asm volatile("cp.async.wait_group 0;"); }

// ---------------------------------------------------------------------------
__global__ void zero_kernel() {
    int i = blockIdx.x * blockDim.x + threadIdx.x;
    if (i < NTOT / 4) ((unsigned int*)g_mask)[i] = 0u;
    if (i < 2) g_accum[i] = 0.0f;
}

__global__ void scatter_kernel(const int* __restrict__ rand_index, int n) {
    int i = blockIdx.x * blockDim.x + threadIdx.x;
    if (i < n) g_mask[rand_index[i]] = 1;
}

// Pack weights into bf16x2 B-fragment layout (col-major, padded pitch).
__global__ void pack_kernel(const float* __restrict__ W1,
                            const float* __restrict__ W2) {
    int i = blockIdx.x * blockDim.x + threadIdx.x;
    if (i < WP1_WORDS) {
        int col = i / W1_LDW, w = i % W1_LDW;
        unsigned int v = 0u;
        if (w < DIM_F / 2)
            v = pk_bf16x2(W1[(size_t)(2 * w) * HID + col],
                          W1[(size_t)(2 * w + 1) * HID + col]);
        g_wp1[i] = v;
    }
    int j = i - WP1_WORDS;
    if (j >= 0 && j < WP2_WORDS) {
        int col = j / W2_LDW, w = j % W2_LDW;
        unsigned int v = 0u;
        if (w < HID / 2)
            v = pk_bf16x2(W2[(size_t)(2 * w) * DIM_E + col],
                          W2[(size_t)(2 * w + 1) * DIM_E + col]);
        g_wp2[j] = v;
    }
}

// ---------------------------------------------------------------------------
// Persistent BF16 tensor-core encoder. 148 CTAs, each loops over row tiles.
// Weights staged to SMEM ONCE per CTA; next tile's v_feat prefetched into
// registers during layer-2 compute.
// Layer1 (128x256x128): warps 2m x 8n, warp tile 64x32.
// Layer2 (128x 64x256): warps 4m x 4n, warp tile 32x16.
// ---------------------------------------------------------------------------
__global__ void __launch_bounds__(THREADS, 1) encoder_kernel(
    const float* __restrict__ v_feat,
    const float* __restrict__ b1, const float* __restrict__ b2)
{
    extern __shared__ uint32_t smu[];
    uint32_t* Wp1s = smu;                       // [256][W1_LDW]
    uint32_t* Wp2s = Wp1s + WP1_WORDS;          // [ 64][W2_LDW]
    uint32_t* As   = Wp2s + WP2_WORDS;          // [128][AS_LDW]
    uint32_t* Hs   = As + AS_WORDS;             // [128][HS_LDW]
    float*    b1s  = (float*)(Hs + HS_WORDS);   // [256]
    float*    b2s  = b1s + HID;                 // [64]

    const int tid  = threadIdx.x;
    const int lane = tid & 31;
    const int warp = tid >> 5;
    const int g    = lane >> 2;       // 0..7
    const int t    = lane & 3;        // 0..3
    const int lrow = lane & 7;        // ldmatrix row-in-tile
    const int lsel = lane >> 3;       // ldmatrix matrix select 0..3

    // ---- stage packed weights into SMEM ONCE (linear cp.async) ----
    for (int i = tid; i < WP1_WORDS / 4; i += THREADS)
        cp_async16(Wp1s + i * 4, g_wp1 + i * 4);
    for (int i = tid; i < WP2_WORDS / 4; i += THREADS)
        cp_async16(Wp2s + i * 4, g_wp2 + i * 4);
    cp_commit();

    if (tid < HID)   b1s[tid] = b1[tid];
    if (tid < DIM_E) b2s[tid] = b2[tid];

    // B ldmatrix lane mapping
    const int bcol1 = (lsel >> 1) * 8 + lrow;
    const int bkh   = (lsel & 1) * 4;
    const int mrow  = (warp >> 3) * 64;    // layer1: 0 or 64
    const int nbase = (warp & 7) * 32;     // layer1: 0..224
    const int mrow2 = (warp >> 2) * 32;    // layer2: 0..96
    const int nb2   = (warp & 3) * 16;     // layer2: 0..48

    // ---- prefetch first tile's v_feat rows into registers ----
    float4 v[8];
    {
        int row0 = blockIdx.x * MTILE;
        #pragma unroll
        for (int i = 0; i < 8; i++) {
            int gc = min(row0 + warp * 8 + i, NUM_ITEM - 1);
            v[i] = ((const float4*)(v_feat + (size_t)gc * DIM_F))[lane];
        }
    }

    cp_wait0();
    __syncthreads();

    for (int tile = blockIdx.x; tile < NTILES; tile += ENC_GRID) {
        const int row0 = tile * MTILE;

        // ---- normalize prefetched rows -> As as bf16x2 ----
        #pragma unroll
        for (int i = 0; i < 8; i++) {
            int r = warp * 8 + i;
            float4 x = v[i];
            float ss = x.x * x.x + x.y * x.y + x.z * x.z + x.w * x.w;
            #pragma unroll
            for (int o = 16; o; o >>= 1) ss += __shfl_xor_sync(0xffffffffu, ss, o);
            float inv = 1.0f / fmaxf(sqrtf(ss), 1e-12f);
            uint2 w2;
            w2.x = pk_bf16x2(x.x * inv, x.y * inv);
            w2.y = pk_bf16x2(x.z * inv, x.w * inv);
            *(uint2*)(As + r * AS_LDW + lane * 2) = w2;
        }
        __syncthreads();

        // ================= layer 1 =================
        float acc1[4][4][4];
        #pragma unroll
        for (int mt = 0; mt < 4; mt++)
            #pragma unroll
            for (int nt = 0; nt < 4; nt++)
                #pragma unroll
                for (int q = 0; q < 4; q++) acc1[mt][nt][q] = 0.0f;

        #pragma unroll
        for (int ks = 0; ks < DIM_F / 16; ks++) {        // 8 k-steps
            uint32_t a[4][4];
            #pragma unroll
            for (int mt = 0; mt < 4; mt++)
                ldsm_x4(a[mt], As + (mrow + mt * 16 + lrow + (lsel & 1) * 8) * AS_LDW
                                  + ks * 8 + (lsel >> 1) * 4);
            #pragma unroll
            for (int bm = 0; bm < 2; bm++) {
                uint32_t bb[4];
                ldsm_x4(bb, Wp1s + (nbase + bm * 16 + bcol1) * W1_LDW + ks * 8 + bkh);
                #pragma unroll
                for (int n2 = 0; n2 < 2; n2++) {
                    int nt = bm * 2 + n2;
                    #pragma unroll
                    for (int mt = 0; mt < 4; mt++)
                        mma_bf16(acc1[mt][nt], a[mt], bb[n2 * 2], bb[n2 * 2 + 1]);
                }
            }
        }

        // epilogue 1: bias + leaky_relu -> Hs (bf16x2)
        #pragma unroll
        for (int mt = 0; mt < 4; mt++) {
            #pragma unroll
            for (int nt = 0; nt < 4; nt++) {
                int r   = mrow + mt * 16 + g;
                int col = nbase + nt * 8 + 2 * t;
                float x0 = acc1[mt][nt][0] + b1s[col];
                float x1 = acc1[mt][nt][1] + b1s[col + 1];
                float x2 = acc1[mt][nt][2] + b1s[col];
                float x3 = acc1[mt][nt][3] + b1s[col + 1];
                x0 = (x0 > 0.0f) ? x0 : 0.01f * x0;
                x1 = (x1 > 0.0f) ? x1 : 0.01f * x1;
                x2 = (x2 > 0.0f) ? x2 : 0.01f * x2;
                x3 = (x3 > 0.0f) ? x3 : 0.01f * x3;
                int wofs = (nbase >> 1) + nt * 4 + t;
                Hs[r * HS_LDW + wofs]       = pk_bf16x2(x0, x1);
                Hs[(r + 8) * HS_LDW + wofs] = pk_bf16x2(x2, x3);
            }
        }
        __syncthreads();

        // ---- prefetch NEXT tile's rows (latency hidden by layer 2) ----
        {
            int ntile = tile + ENC_GRID;
            if (ntile < NTILES) {
                int nr0 = ntile * MTILE;
                #pragma unroll
                for (int i = 0; i < 8; i++) {
                    int gc = min(nr0 + warp * 8 + i, NUM_ITEM - 1);
                    v[i] = ((const float4*)(v_feat + (size_t)gc * DIM_F))[lane];
                }
            }
        }

        // ================= layer 2 =================
        float acc2[2][2][4];
        #pragma unroll
        for (int mt = 0; mt < 2; mt++)
            #pragma unroll
            for (int nt = 0; nt < 2; nt++)
                #pragma unroll
                for (int q = 0; q < 4; q++) acc2[mt][nt][q] = 0.0f;

        #pragma unroll
        for (int ks = 0; ks < HID / 16; ks++) {          // 16 k-steps
            uint32_t h[2][4];
            #pragma unroll
            for (int mt = 0; mt < 2; mt++)
                ldsm_x4(h[mt], Hs + (mrow2 + mt * 16 + lrow + (lsel & 1) * 8) * HS_LDW
                                  + ks * 8 + (lsel >> 1) * 4);
            uint32_t bb[4];
            ldsm_x4(bb, Wp2s + (nb2 + bcol1) * W2_LDW + ks * 8 + bkh);
            #pragma unroll
            for (int nt = 0; nt < 2; nt++) {
                #pragma unroll
                for (int mt = 0; mt < 2; mt++)
                    mma_bf16(acc2[mt][nt], h[mt], bb[nt * 2], bb[nt * 2 + 1]);
            }
        }
        __syncthreads();   // Hs/As free for next iteration

        // epilogue 2: + b2 -> g_feature (registers + read-only smem only)
        #pragma unroll
        for (int mt = 0; mt < 2; mt++) {
            #pragma unroll
            for (int nt = 0; nt < 2; nt++) {
                int r   = row0 + mrow2 + mt * 16 + g;
                int col = nb2 + nt * 8 + 2 * t;
                float2 lo = make_float2(acc2[mt][nt][0] + b2s[col],
                                        acc2[mt][nt][1] + b2s[col + 1]);
                float2 hi = make_float2(acc2[mt][nt][2] + b2s[col],
                                        acc2[mt][nt][3] + b2s[col + 1]);
                if (r < NUM_ITEM)
                    *(float2*)(g_feature + (size_t)r * DIM_E + col) = lo;
                if (r + 8 < NUM_ITEM)
                    *(float2*)(g_feature + (size_t)(r + 8) * DIM_E + col) = hi;
            }
        }
    }
}

// ---------------------------------------------------------------------------
// Loss: one warp per batch row (17 pairs). Lanes cover 64 dims as float2.
// ---------------------------------------------------------------------------
__global__ void __launch_bounds__(256) loss_kernel(
    const float* __restrict__ id_emb,
    const int*   __restrict__ user_t,
    const int*   __restrict__ item_t)
{
    __shared__ float bs[2];
    if (threadIdx.x == 0) { bs[0] = 0.0f; bs[1] = 0.0f; }
    __syncthreads();

    int warp = (blockIdx.x * blockDim.x + threadIdx.x) >> 5;
    int lane = threadIdx.x & 31;

    if (warp < BATCH) {
        int base = warp * GRP;
        int pit  = item_t[base];
        float2 pe = ((const float2*)(id_emb + (size_t)pit * DIM_E))[lane];
        float ps = fmaf(pe.x, pe.x, pe.y * pe.y);
        #pragma unroll
        for (int o = 16; o; o >>= 1) ps += __shfl_xor_sync(0xffffffffu, ps, o);
        float inv_p = 1.0f / fmaxf(sqrtf(ps), 1e-12f);

        float tot1 = 0.0f, tot2 = 0.0f, pos1 = 0.0f, pos2 = 0.0f;
        #pragma unroll 4
        for (int gi = 0; gi < GRP; ++gi) {
            int it = item_t[base + gi];
            int u  = user_t[base + gi];
            int item = it - NUM_USER;
            item = min(max(item, 0), NUM_ITEM - 1);

            float2 f  = ((const float2*)(g_feature + (size_t)item * DIM_E))[lane];
            float2 ue = ((const float2*)(id_emb + (size_t)u * DIM_E))[lane];
            float2 av;
            if (g_mask[base + gi]) av = f;
            else av = ((const float2*)(id_emb + (size_t)it * DIM_E))[lane];

            float fn = fmaf(f.x, f.x, f.y * f.y);
            float d1 = fmaf(pe.x, f.x, pe.y * f.y);
            float d2 = fmaf(ue.x, av.x, ue.y * av.y);
            #pragma unroll
            for (int o = 16; o; o >>= 1) {
                fn += __shfl_xor_sync(0xffffffffu, fn, o);
                d1 += __shfl_xor_sync(0xffffffffu, d1, o);
                d2 += __shfl_xor_sync(0xffffffffu, d2, o);
            }
            float inv_f = 1.0f / fmaxf(sqrtf(fn), 1e-12f);
            float s1 = expf(d1 * inv_p * inv_f * 5.0f);
            float s2 = expf(d2 * 5.0f);
            tot1 += s1; tot2 += s2;
            if (gi == 0) { pos1 = s1; pos2 = s2; }
        }
        if (lane == 0) {
            atomicAdd(&bs[0], -logf(pos1 / (tot1 + 1e-8f) + 1e-8f));
            atomicAdd(&bs[1], -logf(pos2 / (tot2 + 1e-8f) + 1e-8f));
        }
    }
    __syncthreads();
    if (threadIdx.x == 0) {
        atomicAdd(&g_accum[0], bs[0]);
        atomicAdd(&g_accum[1], bs[1]);
    }
}

// ---------------------------------------------------------------------------
__global__ void finalize_kernel(float* __restrict__ out, int n) {
    float v = (g_accum[0] + g_accum[1]) * (0.5f / (float)BATCH);
    for (int i = threadIdx.x; i < n; i += blockDim.x) out[i] = v;
}

// ---------------------------------------------------------------------------
extern "C" void kernel_launch(void* const* d_in, const int* in_sizes, int n_in,
                              void* d_out, int out_size)
{
    const float* v_feat = (const float*)d_in[0];
    const float* id_emb = (const float*)d_in[1];
    const float* W1     = (const float*)d_in[2];
    const float* b1     = (const float*)d_in[3];
    const float* W2     = (const float*)d_in[4];
    const float* b2     = (const float*)d_in[5];
    const int*   user_t = (const int*)d_in[6];
    const int*   item_t = (const int*)d_in[7];
    const int*   rand_i = (const int*)d_in[8];
    const int    n_rand = in_sizes[8];
    float*       out    = (float*)d_out;

    const size_t smem = (size_t)SMEM_WORDS * 4;   // ~207 KB
    cudaFuncSetAttribute(encoder_kernel,
                         cudaFuncAttributeMaxDynamicSharedMemorySize, (int)smem);

    zero_kernel<<<(NTOT / 4 + 255) / 256, 256>>>();
    scatter_kernel<<<(n_rand + 255) / 256, 256>>>(rand_i, n_rand);
    pack_kernel<<<(WP1_WORDS + WP2_WORDS + 255) / 256, 256>>>(W1, W2);
    encoder_kernel<<<ENC_GRID, THREADS, smem>>>(v_feat, b1, b2);
    loss_kernel<<<BATCH / 8, 256>>>(id_emb, user_t, item_t);
    finalize_kernel<<<1, 32>>>(out, out_size > 0 ? out_size : 1);
}

// round 16
// speedup vs baseline: 1.4901x; 1.1490x over previous
#include <cuda_runtime.h>
#include <cuda_bf16.h>
#include <math.h>
#include <stdint.h>

#define NUM_USER 200000
#define NUM_ITEM 200000
#define DIM_E    64
#define DIM_F    128
#define HID      256
#define BATCH    16384
#define GRP      17
#define NTOT     (BATCH * GRP)   // 278528

#define MTILE    64
#define THREADS  256
#define ENC_GRID 296             // 2 CTAs per SM
#define NTILES   (NUM_ITEM / MTILE)   // 3125 exact

#define AS_LDW   68    // As pitch in words (64 data + 4 pad), 68%32==4
#define HS_LDW   132   // Hs pitch (128 data + 4 pad), 132%32==4

#define AS_WORDS  (MTILE * AS_LDW)    // 4352
#define HS_WORDS  (MTILE * HS_LDW)    // 8448
#define SMEM_WORDS (AS_WORDS + HS_WORDS + HID + DIM_E)   // 13120 -> 52.5KB

#define WB1_FRAGS (16 * 8 * 32)       // [bm16][ks][lane] uint4
#define WB2_FRAGS (4 * 16 * 32)       // [bm16][ks][lane] uint4

// Scratch (static device globals: allocation-free per harness rules)
__device__ float         g_feature[(size_t)NUM_ITEM * DIM_E];  // 51.2 MB
__device__ uint4         g_wb1[WB1_FRAGS];   // 64 KB packed W1 B-frags
__device__ uint4         g_wb2[WB2_FRAGS];   // 32 KB packed W2 B-frags
__device__ unsigned char g_mask[NTOT];
__device__ float         g_accum[2];

// ---------------------------------------------------------------------------
__device__ __forceinline__ uint32_t pk_bf16x2(float lo, float hi) {
    __nv_bfloat162 h = __floats2bfloat162_rn(lo, hi);
    return *reinterpret_cast<uint32_t*>(&h);
}

__device__ __forceinline__ void mma_bf16(float* c, const uint32_t* a,
                                         uint32_t b0, uint32_t b1) {
    asm volatile(
        "mma.sync.aligned.m16n8k16.row.col.f32.bf16.bf16.f32 "
        "{%0,%1,%2,%3},{%4,%5,%6,%7},{%8,%9},{%0,%1,%2,%3};"
        : "+f"(c[0]), "+f"(c[1]), "+f"(c[2]), "+f"(c[3])
        : "r"(a[0]), "r"(a[1]), "r"(a[2]), "r"(a[3]), "r"(b0), "r"(b1));
}

__device__ __forceinline__ void ldsm_x4(uint32_t* a, const uint32_t* p) {
    uint32_t s = (uint32_t)__cvta_generic_to_shared(p);
    asm volatile("ldmatrix.sync.aligned.m8n8.x4.shared.b16 {%0,%1,%2,%3},[%4];"
                 : "=r"(a[0]), "=r"(a[1]), "=r"(a[2]), "=r"(a[3]) : "r"(s));
}

// ---------------------------------------------------------------------------
__global__ void zero_kernel() {
    int i = blockIdx.x * blockDim.x + threadIdx.x;
    if (i < NTOT / 4) ((unsigned int*)g_mask)[i] = 0u;
    if (i < 2) g_accum[i] = 0.0f;
}

__global__ void scatter_kernel(const int* __restrict__ rand_index, int n) {
    int i = blockIdx.x * blockDim.x + threadIdx.x;
    if (i < n) g_mask[rand_index[i]] = 1;
}

// Pack weights into per-lane uint4 B-fragment lines.
// Frag layout (u.x,u.y,u.z,u.w) for lane l, 16-col group bm, k-step ks:
//   col = bm*16 + (l>>2); kwA = ks*8 + (l&3); kwB = kwA + 4
//   u.x = W[kwA pair][col]   u.y = W[kwB pair][col]
//   u.z = W[kwA pair][col+8] u.w = W[kwB pair][col+8]
__global__ void pack_kernel(const float* __restrict__ W1,
                            const float* __restrict__ W2) {
    int i = blockIdx.x * blockDim.x + threadIdx.x;
    if (i < WB1_FRAGS) {
        int lane = i & 31, ks = (i >> 5) & 7, bm = i >> 8;
        int col = bm * 16 + (lane >> 2);
        int kwA = ks * 8 + (lane & 3), kwB = kwA + 4;
        uint4 u;
        u.x = pk_bf16x2(W1[(size_t)(2 * kwA) * HID + col],
                        W1[(size_t)(2 * kwA + 1) * HID + col]);
        u.y = pk_bf16x2(W1[(size_t)(2 * kwB) * HID + col],
                        W1[(size_t)(2 * kwB + 1) * HID + col]);
        u.z = pk_bf16x2(W1[(size_t)(2 * kwA) * HID + col + 8],
                        W1[(size_t)(2 * kwA + 1) * HID + col + 8]);
        u.w = pk_bf16x2(W1[(size_t)(2 * kwB) * HID + col + 8],
                        W1[(size_t)(2 * kwB + 1) * HID + col + 8]);
        g_wb1[i] = u;
    }
    int j = i - WB1_FRAGS;
    if (j >= 0 && j < WB2_FRAGS) {
        int lane = j & 31, ks = (j >> 5) & 15, bm = j >> 9;
        int col = bm * 16 + (lane >> 2);
        int kwA = ks * 8 + (lane & 3), kwB = kwA + 4;
        uint4 u;
        u.x = pk_bf16x2(W2[(size_t)(2 * kwA) * DIM_E + col],
                        W2[(size_t)(2 * kwA + 1) * DIM_E + col]);
        u.y = pk_bf16x2(W2[(size_t)(2 * kwB) * DIM_E + col],
                        W2[(size_t)(2 * kwB + 1) * DIM_E + col]);
        u.z = pk_bf16x2(W2[(size_t)(2 * kwA) * DIM_E + col + 8],
                        W2[(size_t)(2 * kwA + 1) * DIM_E + col + 8]);
        u.w = pk_bf16x2(W2[(size_t)(2 * kwB) * DIM_E + col + 8],
                        W2[(size_t)(2 * kwB + 1) * DIM_E + col + 8]);
        g_wb2[j] = u;
    }
}

// ---------------------------------------------------------------------------
// Persistent BF16 encoder, 2 CTAs/SM. CTA = 64 rows, 8 warps.
// B-frags via per-lane LDG.128 from packed gmem (L1-resident, no smem).
// Layer1 (64x256x128): warps 1m x 8n, warp tile 64x32 (mt=4, nt=4).
// Layer2 (64x 64x256): warps 2m x 4n, warp tile 32x16 (mt=2, nt=2).
// ---------------------------------------------------------------------------
__global__ void __launch_bounds__(THREADS, 2) encoder_kernel(
    const float* __restrict__ v_feat,
    const float* __restrict__ b1, const float* __restrict__ b2)
{
    extern __shared__ uint32_t smu[];
    uint32_t* As  = smu;                      // [64][AS_LDW]
    uint32_t* Hs  = As + AS_WORDS;            // [64][HS_LDW]
    float*    b1s = (float*)(Hs + HS_WORDS);  // [256]
    float*    b2s = b1s + HID;                // [64]

    const int tid  = threadIdx.x;
    const int lane = tid & 31;
    const int warp = tid >> 5;
    const int g    = lane >> 2;
    const int t    = lane & 3;
    const int lrow = lane & 7;
    const int lsel = lane >> 3;

    if (tid < HID)   b1s[tid] = b1[tid];
    if (tid < DIM_E) b2s[tid] = b2[tid];

    const int nbase = warp * 32;           // layer1 n-offset
    const int mrow2 = (warp >> 2) * 32;    // layer2 m-offset
    const int nb2   = (warp & 3) * 16;     // layer2 n-offset
    const int bm2   = warp & 3;            // layer2 16-col group

    // ---- prefetch first tile's v_feat rows ----
    float4 v[8];
    {
        int row0 = blockIdx.x * MTILE;
        #pragma unroll
        for (int i = 0; i < 8; i++)
            v[i] = ((const float4*)(v_feat + (size_t)(row0 + warp * 8 + i) * DIM_F))[lane];
    }

    for (int tile = blockIdx.x; tile < NTILES; tile += ENC_GRID) {
        const int row0 = tile * MTILE;

        // ---- normalize prefetched rows -> As (bf16x2) ----
        #pragma unroll
        for (int i = 0; i < 8; i++) {
            int r = warp * 8 + i;
            float4 x = v[i];
            float ss = x.x * x.x + x.y * x.y + x.z * x.z + x.w * x.w;
            #pragma unroll
            for (int o = 16; o; o >>= 1) ss += __shfl_xor_sync(0xffffffffu, ss, o);
            float inv = 1.0f / fmaxf(sqrtf(ss), 1e-12f);
            uint2 w2;
            w2.x = pk_bf16x2(x.x * inv, x.y * inv);
            w2.y = pk_bf16x2(x.z * inv, x.w * inv);
            *(uint2*)(As + r * AS_LDW + lane * 2) = w2;
        }
        __syncthreads();

        // ================= layer 1 =================
        float acc1[4][4][4];
        #pragma unroll
        for (int mt = 0; mt < 4; mt++)
            #pragma unroll
            for (int nt = 0; nt < 4; nt++)
                #pragma unroll
                for (int q = 0; q < 4; q++) acc1[mt][nt][q] = 0.0f;

        #pragma unroll
        for (int ks = 0; ks < DIM_F / 16; ks++) {        // 8 k-steps
            uint32_t a[4][4];
            #pragma unroll
            for (int mt = 0; mt < 4; mt++)
                ldsm_x4(a[mt], As + (mt * 16 + lrow + (lsel & 1) * 8) * AS_LDW
                                  + ks * 8 + (lsel >> 1) * 4);
            #pragma unroll
            for (int bm = 0; bm < 2; bm++) {
                uint4 bb = __ldg(&g_wb1[(((nbase >> 4) + bm) * 8 + ks) * 32 + lane]);
                #pragma unroll
                for (int mt = 0; mt < 4; mt++)
                    mma_bf16(acc1[mt][bm * 2], a[mt], bb.x, bb.y);
                #pragma unroll
                for (int mt = 0; mt < 4; mt++)
                    mma_bf16(acc1[mt][bm * 2 + 1], a[mt], bb.z, bb.w);
            }
        }

        // epilogue 1: bias + leaky_relu -> Hs (bf16x2)
        #pragma unroll
        for (int mt = 0; mt < 4; mt++) {
            #pragma unroll
            for (int nt = 0; nt < 4; nt++) {
                int r   = mt * 16 + g;
                int col = nbase + nt * 8 + 2 * t;
                float x0 = acc1[mt][nt][0] + b1s[col];
                float x1 = acc1[mt][nt][1] + b1s[col + 1];
                float x2 = acc1[mt][nt][2] + b1s[col];
                float x3 = acc1[mt][nt][3] + b1s[col + 1];
                x0 = (x0 > 0.0f) ? x0 : 0.01f * x0;
                x1 = (x1 > 0.0f) ? x1 : 0.01f * x1;
                x2 = (x2 > 0.0f) ? x2 : 0.01f * x2;
                x3 = (x3 > 0.0f) ? x3 : 0.01f * x3;
                int wofs = (nbase >> 1) + nt * 4 + t;
                Hs[r * HS_LDW + wofs]       = pk_bf16x2(x0, x1);
                Hs[(r + 8) * HS_LDW + wofs] = pk_bf16x2(x2, x3);
            }
        }
        __syncthreads();

        // ---- prefetch NEXT tile's rows (hidden by layer 2) ----
        {
            int ntile = tile + ENC_GRID;
            if (ntile < NTILES) {
                int nr0 = ntile * MTILE;
                #pragma unroll
                for (int i = 0; i < 8; i++)
                    v[i] = ((const float4*)(v_feat + (size_t)(nr0 + warp * 8 + i) * DIM_F))[lane];
            }
        }

        // ================= layer 2 =================
        float acc2[2][2][4];
        #pragma unroll
        for (int mt = 0; mt < 2; mt++)
            #pragma unroll
            for (int nt = 0; nt < 2; nt++)
                #pragma unroll
                for (int q = 0; q < 4; q++) acc2[mt][nt][q] = 0.0f;

        #pragma unroll
        for (int ks = 0; ks < HID / 16; ks++) {          // 16 k-steps
            uint32_t h[2][4];
            #pragma unroll
            for (int mt = 0; mt < 2; mt++)
                ldsm_x4(h[mt], Hs + (mrow2 + mt * 16 + lrow + (lsel & 1) * 8) * HS_LDW
                                  + ks * 8 + (lsel >> 1) * 4);
            uint4 bb = __ldg(&g_wb2[(bm2 * 16 + ks) * 32 + lane]);
            #pragma unroll
            for (int mt = 0; mt < 2; mt++)
                mma_bf16(acc2[mt][0], h[mt], bb.x, bb.y);
            #pragma unroll
            for (int mt = 0; mt < 2; mt++)
                mma_bf16(acc2[mt][1], h[mt], bb.z, bb.w);
        }

        // epilogue 2 (regs + read-only b2s): store before the sync
        #pragma unroll
        for (int mt = 0; mt < 2; mt++) {
            #pragma unroll
            for (int nt = 0; nt < 2; nt++) {
                int r   = row0 + mrow2 + mt * 16 + g;
                int col = nb2 + nt * 8 + 2 * t;
                float2 lo = make_float2(acc2[mt][nt][0] + b2s[col],
                                        acc2[mt][nt][1] + b2s[col + 1]);
                float2 hi = make_float2(acc2[mt][nt][2] + b2s[col],
                                        acc2[mt][nt][3] + b2s[col + 1]);
                *(float2*)(g_feature + (size_t)r * DIM_E + col)       = lo;
                *(float2*)(g_feature + (size_t)(r + 8) * DIM_E + col) = hi;
            }
        }
        __syncthreads();   // Hs free for next iteration's As/Hs writes
    }
}

// ---------------------------------------------------------------------------
// Loss: 2 rows per warp, 16 lanes x float4 per row. 4-stage reductions.
// ---------------------------------------------------------------------------
__global__ void __launch_bounds__(256) loss_kernel(
    const float* __restrict__ id_emb,
    const int*   __restrict__ user_t,
    const int*   __restrict__ item_t)
{
    __shared__ float bs[2];
    if (threadIdx.x == 0) { bs[0] = 0.0f; bs[1] = 0.0f; }
    __syncthreads();

    int warp = (blockIdx.x * blockDim.x + threadIdx.x) >> 5;
    int lane = threadIdx.x & 31;
    int hh   = lane >> 4;      // half-warp: row select
    int l16  = lane & 15;      // lane within row (4 dims each)

    int row = warp * 2 + hh;
    if (row < BATCH) {
        int base = row * GRP;
        int pit  = item_t[base];
        float4 pe = ((const float4*)(id_emb + (size_t)pit * DIM_E))[l16];
        float ps = pe.x * pe.x + pe.y * pe.y + pe.z * pe.z + pe.w * pe.w;
        #pragma unroll
        for (int o = 8; o; o >>= 1) ps += __shfl_xor_sync(0xffffffffu, ps, o);
        float inv_p = 1.0f / fmaxf(sqrtf(ps), 1e-12f);

        float tot1 = 0.0f, tot2 = 0.0f, pos1 = 0.0f, pos2 = 0.0f;
        #pragma unroll 4
        for (int gi = 0; gi < GRP; ++gi) {
            int it = item_t[base + gi];
            int u  = user_t[base + gi];
            int item = min(max(it - NUM_USER, 0), NUM_ITEM - 1);

            float4 f  = ((const float4*)(g_feature + (size_t)item * DIM_E))[l16];
            float4 ue = ((const float4*)(id_emb + (size_t)u * DIM_E))[l16];
            float4 av;
            if (g_mask[base + gi]) av = f;
            else av = ((const float4*)(id_emb + (size_t)it * DIM_E))[l16];

            float fn = f.x * f.x + f.y * f.y + f.z * f.z + f.w * f.w;
            float d1 = pe.x * f.x + pe.y * f.y + pe.z * f.z + pe.w * f.w;
            float d2 = ue.x * av.x + ue.y * av.y + ue.z * av.z + ue.w * av.w;
            #pragma unroll
            for (int o = 8; o; o >>= 1) {
                fn += __shfl_xor_sync(0xffffffffu, fn, o);
                d1 += __shfl_xor_sync(0xffffffffu, d1, o);
                d2 += __shfl_xor_sync(0xffffffffu, d2, o);
            }
            float inv_f = 1.0f / fmaxf(sqrtf(fn), 1e-12f);
            float s1 = __expf(d1 * inv_p * inv_f * 5.0f);   // 1/TEMP = 5
            float s2 = __expf(d2 * 5.0f);
            tot1 += s1; tot2 += s2;
            if (gi == 0) { pos1 = s1; pos2 = s2; }
        }
        if (l16 == 0) {
            atomicAdd(&bs[0], -__logf(pos1 / (tot1 + 1e-8f) + 1e-8f));
            atomicAdd(&bs[1], -__logf(pos2 / (tot2 + 1e-8f) + 1e-8f));
        }
    }
    __syncthreads();
    if (threadIdx.x == 0) {
        atomicAdd(&g_accum[0], bs[0]);
        atomicAdd(&g_accum[1], bs[1]);
    }
}

// ---------------------------------------------------------------------------
__global__ void finalize_kernel(float* __restrict__ out, int n) {
    float v = (g_accum[0] + g_accum[1]) * (0.5f / (float)BATCH);
    for (int i = threadIdx.x; i < n; i += blockDim.x) out[i] = v;
}

// ---------------------------------------------------------------------------
extern "C" void kernel_launch(void* const* d_in, const int* in_sizes, int n_in,
                              void* d_out, int out_size)
{
    const float* v_feat = (const float*)d_in[0];
    const float* id_emb = (const float*)d_in[1];
    const float* W1     = (const float*)d_in[2];
    const float* b1     = (const float*)d_in[3];
    const float* W2     = (const float*)d_in[4];
    const float* b2     = (const float*)d_in[5];
    const int*   user_t = (const int*)d_in[6];
    const int*   item_t = (const int*)d_in[7];
    const int*   rand_i = (const int*)d_in[8];
    const int    n_rand = in_sizes[8];
    float*       out    = (float*)d_out;

    const size_t smem = (size_t)SMEM_WORDS * 4;   // 52.5 KB -> 2 CTAs/SM
    cudaFuncSetAttribute(encoder_kernel,
                         cudaFuncAttributeMaxDynamicSharedMemorySize, (int)smem);

    zero_kernel<<<(NTOT / 4 + 255) / 256, 256>>>();
    scatter_kernel<<<(n_rand + 255) / 256, 256>>>(rand_i, n_rand);
    pack_kernel<<<(WB1_FRAGS + WB2_FRAGS + 255) / 256, 256>>>(W1, W2);
    encoder_kernel<<<ENC_GRID, THREADS, smem>>>(v_feat, b1, b2);
    loss_kernel<<<BATCH / 16, 256>>>(id_emb, user_t, item_t);
    finalize_kernel<<<1, 32>>>(out, out_size > 0 ? out_size : 1);
}